// round 16
// baseline (speedup 1.0000x reference)
#include <cuda_runtime.h>
#include <cuda_bf16.h>
#include <cuda_fp16.h>
#include <cstdint>

// ---------------- problem constants ----------------
static constexpr int NB  = 16;
static constexpr int SEQ = 2048;
static constexpr int DIM = 128;
static constexpr size_t NEL = (size_t)NB * SEQ * DIM;   // 4,194,304

// BLOCK_M=128, 512 threads (16 warps: 8 row-slices x 2 dv/key halves), BLK_N=64
static constexpr int BLK_N   = 64;
static constexpr int NIT     = SEQ / BLK_N;             // 32
static constexpr uint32_t ROWB    = 272;                // 256B data + 16B pad
static constexpr uint32_t TILE_B  = 64 * ROWB;          // 17408
static constexpr uint32_t STAGE_B = 3 * TILE_B;         // Khi, Klo, Vh = 52224
static constexpr uint32_t QTILE_B = 128 * ROWB;         // 34816
static constexpr uint32_t PROWB   = 144;                // 128B P row + 16B pad
// smem layout
static constexpr uint32_t SM_QHI  = 0;
static constexpr uint32_t SM_QLO  = QTILE_B;            // 34816
static constexpr uint32_t SM_P    = 2 * QTILE_B;        // 69632
static constexpr uint32_t SM_MX   = SM_P + 128 * PROWB; // 88064 (float[128][2])
static constexpr uint32_t SM_RS   = SM_MX + 1024;       // 89088
static constexpr uint32_t SM_RING = 90112;              // 1KB-aligned
static constexpr uint32_t SMEM_BYTES = SM_RING + 2 * STAGE_B;  // 194560

// ---------------- static device scratch (no allocs) ----------------
__device__ __align__(256) __nv_bfloat16 g_Khi[NEL];
__device__ __align__(256) __nv_bfloat16 g_Klo[NEL];
__device__ __align__(256) __half        g_Vh [NEL];

// ---------------- PTX helpers (base compute_103) ----------------
__device__ __forceinline__ uint32_t smem_u32(const void* p) {
    uint32_t a;
    asm("{ .reg .u64 t; cvta.to.shared.u64 t, %1; cvt.u32.u64 %0, t; }" : "=r"(a) : "l"(p));
    return a;
}
#define CP16(sm, gp) asm volatile("cp.async.cg.shared.global [%0], [%1], 16;" :: "r"(sm), "l"(gp))
#define CP_COMMIT()  asm volatile("cp.async.commit_group;" ::: "memory")
#define CP_WAIT1()   asm volatile("cp.async.wait_group 1;" ::: "memory")
#define CP_WAIT0()   asm volatile("cp.async.wait_group 0;" ::: "memory")
#define PAIR_BAR(id) asm volatile("bar.sync %0, 64;" :: "r"(id) : "memory")

__device__ __forceinline__ void ldm_x4(uint32_t* r, uint32_t addr) {
    asm volatile("ldmatrix.sync.aligned.m8n8.x4.shared.b16 {%0,%1,%2,%3}, [%4];"
                 : "=r"(r[0]), "=r"(r[1]), "=r"(r[2]), "=r"(r[3]) : "r"(addr) : "memory");
}
__device__ __forceinline__ void ldm_x4_t(uint32_t* r, uint32_t addr) {
    asm volatile("ldmatrix.sync.aligned.m8n8.x4.trans.shared.b16 {%0,%1,%2,%3}, [%4];"
                 : "=r"(r[0]), "=r"(r[1]), "=r"(r[2]), "=r"(r[3]) : "r"(addr) : "memory");
}
__device__ __forceinline__ void mma_bf16(float* d, const uint32_t* a, uint32_t b0, uint32_t b1) {
    asm volatile("mma.sync.aligned.m16n8k16.row.col.f32.bf16.bf16.f32 "
                 "{%0,%1,%2,%3}, {%4,%5,%6,%7}, {%8,%9}, {%0,%1,%2,%3};"
                 : "+f"(d[0]), "+f"(d[1]), "+f"(d[2]), "+f"(d[3])
                 : "r"(a[0]), "r"(a[1]), "r"(a[2]), "r"(a[3]), "r"(b0), "r"(b1));
}
__device__ __forceinline__ void mma_f16(float* d, const uint32_t* a, uint32_t b0, uint32_t b1) {
    asm volatile("mma.sync.aligned.m16n8k16.row.col.f32.f16.f16.f32 "
                 "{%0,%1,%2,%3}, {%4,%5,%6,%7}, {%8,%9}, {%0,%1,%2,%3};"
                 : "+f"(d[0]), "+f"(d[1]), "+f"(d[2]), "+f"(d[3])
                 : "r"(a[0]), "r"(a[1]), "r"(a[2]), "r"(a[3]), "r"(b0), "r"(b1));
}

// ---------------- pre-pass: K -> split-bf16, V -> fp16 ----------------
__global__ void __launch_bounds__(512) prepass(const float* __restrict__ x2,
                                               const float* __restrict__ x3) {
    size_t t = (size_t)blockIdx.x * blockDim.x + threadIdx.x;   // over NEL/8
    if (t >= NEL / 8) return;

    #pragma unroll
    for (int h = 0; h < 2; h++) {
        size_t i4 = t * 2 + h;
        size_t i  = i4 * 4;
        float4 k = reinterpret_cast<const float4*>(x2)[i4];
        float4 v = reinterpret_cast<const float4*>(x3)[i4];

        float ka[4] = {k.x, k.y, k.z, k.w};
        __nv_bfloat16 kh[4], kl[4];
        __half vh[4] = {__float2half(v.x), __float2half(v.y),
                        __float2half(v.z), __float2half(v.w)};
        #pragma unroll
        for (int j = 0; j < 4; j++) {
            kh[j] = __float2bfloat16(ka[j]);
            kl[j] = __float2bfloat16(ka[j] - __bfloat162float(kh[j]));
        }
        *reinterpret_cast<uint2*>(g_Khi + i) = *reinterpret_cast<uint2*>(kh);
        *reinterpret_cast<uint2*>(g_Klo + i) = *reinterpret_cast<uint2*>(kl);
        *reinterpret_cast<uint2*>(g_Vh  + i) = *reinterpret_cast<uint2*>(vh);
    }
}

// ---------------- fused flash-attention: 512 threads, pair-split warps ----------------
__global__ void __launch_bounds__(512, 1)
fa_fwd(const float* __restrict__ x1, const float* __restrict__ sfp,
       float* __restrict__ out) {
    extern __shared__ char smem[];
    const uint32_t sb = smem_u32(smem);
    const uint32_t rb = sb + SM_RING;
    const int tid  = threadIdx.x;
    const int w    = tid >> 5;
    const int lane = tid & 31;
    const int pw   = w & 7;           // row-slice id (16 rows)
    const int d    = w >> 3;          // key-half for QK, dv-half for PV
    const int b  = blockIdx.x >> 4;
    const int qt = blockIdx.x & 15;
    const float sf = *sfp;

    const uint32_t k_lane = (uint32_t)((((lane >> 4) & 1) * 8 + (lane & 7)) * ROWB + ((lane >> 3) & 1) * 16);
    const uint32_t v_lane = (uint32_t)((((lane >> 3) & 1) * 8 + (lane & 7)) * ROWB + ((lane >> 4) & 1) * 16);
    const uint32_t q_lane  = (uint32_t)((lane & 15) * ROWB  + (lane >> 4) * 16) + (uint32_t)(pw * 16) * ROWB;
    const uint32_t p_lane  = (uint32_t)((lane & 15) * PROWB + (lane >> 4) * 16) + (uint32_t)(pw * 16) * PROWB;

    // ---- stage Q block into SMEM: fp32 -> scaled split bf16 hi/lo ----
    {
        const size_t qg = ((size_t)b * SEQ + (size_t)qt * 128) * DIM;
        #pragma unroll
        for (int i = tid; i < 128 * 64; i += 512) {
            int row = i >> 6, c2 = (i & 63) * 2;
            float2 v = *reinterpret_cast<const float2*>(x1 + qg + (size_t)row * DIM + c2);
            v.x *= sf; v.y *= sf;
            __nv_bfloat16 hx = __float2bfloat16(v.x), hy = __float2bfloat16(v.y);
            __nv_bfloat162 th; th.x = hx; th.y = hy;
            __nv_bfloat162 tl = __floats2bfloat162_rn(v.x - __bfloat162float(hx),
                                                      v.y - __bfloat162float(hy));
            uint32_t soff = (uint32_t)row * ROWB + (uint32_t)c2 * 2;
            *reinterpret_cast<uint32_t*>(smem + SM_QHI + soff) = *reinterpret_cast<uint32_t*>(&th);
            *reinterpret_cast<uint32_t*>(smem + SM_QLO + soff) = *reinterpret_cast<uint32_t*>(&tl);
        }
    }

    // ---- cp.async tile loader (512 threads) ----
    const size_t kvbase = (size_t)b * SEQ * DIM;
    auto load_tiles = [&](int stage, int kt) {
        const uint32_t s0 = rb + (uint32_t)stage * STAGE_B;
        const size_t g0 = kvbase + (size_t)kt * BLK_N * DIM;
        #pragma unroll
        for (int t = 0; t < 2; t++) {
            int c = tid + t * 512;               // 0..1023
            int row = c >> 4, col = c & 15;
            uint32_t so = (uint32_t)row * ROWB + (uint32_t)col * 16;
            size_t  go = g0 + (size_t)row * DIM + col * 8;
            CP16(s0 +            so, g_Khi + go);
            CP16(s0 + TILE_B   + so, g_Klo + go);
            CP16(s0 + 2*TILE_B + so, g_Vh  + go);
        }
    };

    float o[32];
    #pragma unroll
    for (int j = 0; j < 32; j++) o[j] = 0.0f;
    float m0 = -1e30f, m1 = -1e30f, l0 = 0.0f, l1 = 0.0f;
    float s[16];

    const int r0 = lane >> 2, c0 = (lane & 3) * 2;
    const int grow0 = pw * 16 + r0;            // tile-local row of this thread
    const int bar_id = 1 + pw;

    load_tiles(0, 0); CP_COMMIT();

    #pragma unroll 1
    for (int kt = 0; kt < NIT; kt++) {
        if (kt + 1 < NIT) { load_tiles((kt + 1) & 1, kt + 1); CP_COMMIT(); CP_WAIT1(); }
        else              { CP_WAIT0(); }
        __syncthreads();

        const uint32_t st = rb + (uint32_t)(kt & 1) * STAGE_B;
        const uint32_t aKhi = st + k_lane;
        const uint32_t aKlo = st + TILE_B + k_lane;
        const uint32_t aV   = st + 2 * TILE_B + v_lane + (uint32_t)d * 128;

        // ---- QK over my 32-key half: S = Qhi*Khi + Qlo*Khi + Qhi*Klo ----
        #pragma unroll
        for (int j = 0; j < 16; j++) s[j] = 0.0f;
        #pragma unroll
        for (int kk = 0; kk < 8; kk++) {
            uint32_t qh[4], ql[4], kb[8];
            ldm_x4(qh, sb + SM_QHI + q_lane + (uint32_t)kk * 32);
            ldm_x4(ql, sb + SM_QLO + q_lane + (uint32_t)kk * 32);
            ldm_x4(kb,     aKhi + (uint32_t)(2*d + 0) * 16 * ROWB + (uint32_t)kk * 32);
            ldm_x4(kb + 4, aKhi + (uint32_t)(2*d + 1) * 16 * ROWB + (uint32_t)kk * 32);
            mma_bf16(s + 0,  qh, kb[0], kb[1]);
            mma_bf16(s + 4,  qh, kb[2], kb[3]);
            mma_bf16(s + 8,  qh, kb[4], kb[5]);
            mma_bf16(s + 12, qh, kb[6], kb[7]);
            mma_bf16(s + 0,  ql, kb[0], kb[1]);
            mma_bf16(s + 4,  ql, kb[2], kb[3]);
            mma_bf16(s + 8,  ql, kb[4], kb[5]);
            mma_bf16(s + 12, ql, kb[6], kb[7]);
            ldm_x4(kb,     aKlo + (uint32_t)(2*d + 0) * 16 * ROWB + (uint32_t)kk * 32);
            ldm_x4(kb + 4, aKlo + (uint32_t)(2*d + 1) * 16 * ROWB + (uint32_t)kk * 32);
            mma_bf16(s + 0,  qh, kb[0], kb[1]);
            mma_bf16(s + 4,  qh, kb[2], kb[3]);
            mma_bf16(s + 8,  qh, kb[4], kb[5]);
            mma_bf16(s + 12, qh, kb[6], kb[7]);
        }

        // ---- softmax: merge with partner warp (other key half) ----
        float mx0 = -1e30f, mx1 = -1e30f;
        #pragma unroll
        for (int j = 0; j < 4; j++) {
            mx0 = fmaxf(mx0, fmaxf(s[j*4+0], s[j*4+1]));
            mx1 = fmaxf(mx1, fmaxf(s[j*4+2], s[j*4+3]));
        }
        mx0 = fmaxf(mx0, __shfl_xor_sync(0xffffffffu, mx0, 1));
        mx0 = fmaxf(mx0, __shfl_xor_sync(0xffffffffu, mx0, 2));
        mx1 = fmaxf(mx1, __shfl_xor_sync(0xffffffffu, mx1, 1));
        mx1 = fmaxf(mx1, __shfl_xor_sync(0xffffffffu, mx1, 2));
        if ((lane & 3) == 0) {
            *reinterpret_cast<float*>(smem + SM_MX + ((grow0)     * 2 + d) * 4) = mx0;
            *reinterpret_cast<float*>(smem + SM_MX + ((grow0 + 8) * 2 + d) * 4) = mx1;
        }
        PAIR_BAR(bar_id);
        const float pm0 = *reinterpret_cast<float*>(smem + SM_MX + ((grow0)     * 2 + (1 - d)) * 4);
        const float pm1 = *reinterpret_cast<float*>(smem + SM_MX + ((grow0 + 8) * 2 + (1 - d)) * 4);
        const float mn0 = fmaxf(m0, fmaxf(mx0, pm0));
        const float mn1 = fmaxf(m1, fmaxf(mx1, pm1));
        const float a0 = __expf(m0 - mn0), a1 = __expf(m1 - mn1);
        m0 = mn0; m1 = mn1;

        float rs0 = 0.0f, rs1 = 0.0f;
        #pragma unroll
        for (int nt = 0; nt < 4; nt++) {
            float p0 = __expf(s[nt*4+0] - mn0);
            float p1 = __expf(s[nt*4+1] - mn0);
            float p2 = __expf(s[nt*4+2] - mn1);
            float p3 = __expf(s[nt*4+3] - mn1);
            rs0 += p0 + p1; rs1 += p2 + p3;
            __half2 h01 = __floats2half2_rn(p0, p1);
            __half2 h23 = __floats2half2_rn(p2, p3);
            uint32_t key = (uint32_t)(d * 32 + nt * 8 + c0);
            *reinterpret_cast<uint32_t*>(smem + SM_P + (uint32_t)grow0 * PROWB + key * 2)
                = *reinterpret_cast<uint32_t*>(&h01);
            *reinterpret_cast<uint32_t*>(smem + SM_P + (uint32_t)(grow0 + 8) * PROWB + key * 2)
                = *reinterpret_cast<uint32_t*>(&h23);
        }
        rs0 += __shfl_xor_sync(0xffffffffu, rs0, 1);
        rs0 += __shfl_xor_sync(0xffffffffu, rs0, 2);
        rs1 += __shfl_xor_sync(0xffffffffu, rs1, 1);
        rs1 += __shfl_xor_sync(0xffffffffu, rs1, 2);
        if ((lane & 3) == 0) {
            *reinterpret_cast<float*>(smem + SM_RS + ((grow0)     * 2 + d) * 4) = rs0;
            *reinterpret_cast<float*>(smem + SM_RS + ((grow0 + 8) * 2 + d) * 4) = rs1;
        }
        PAIR_BAR(bar_id);
        const float prs0 = *reinterpret_cast<float*>(smem + SM_RS + ((grow0)     * 2 + (1 - d)) * 4);
        const float prs1 = *reinterpret_cast<float*>(smem + SM_RS + ((grow0 + 8) * 2 + (1 - d)) * 4);
        l0 = l0 * a0 + rs0 + prs0;
        l1 = l1 * a1 + rs1 + prs1;

        #pragma unroll
        for (int j = 0; j < 8; j++) {
            o[j*4+0] *= a0; o[j*4+1] *= a0;
            o[j*4+2] *= a1; o[j*4+3] *= a1;
        }

        // ---- PV: full 64 keys (P from smem), my 64-dv half ----
        #pragma unroll
        for (int kc = 0; kc < 4; kc++) {
            uint32_t pf[4];
            ldm_x4(pf, sb + SM_P + p_lane + (uint32_t)kc * 32);
            #pragma unroll
            for (int g = 0; g < 4; g++) {
                uint32_t vb[4];
                ldm_x4_t(vb, aV + (uint32_t)kc * 16 * ROWB + (uint32_t)g * 32);
                mma_f16(o + (2*g)   * 4, pf, vb[0], vb[1]);
                mma_f16(o + (2*g+1) * 4, pf, vb[2], vb[3]);
            }
        }
        __syncthreads();
    }

    // ---- finalize: l is already full-row; normalize, store my dv half ----
    const float i0 = 1.0f / l0, i1 = 1.0f / l1;
    const size_t row0 = (size_t)b * SEQ + (size_t)qt * 128 + pw * 16 + r0;
    float* out0 = out + row0 * DIM + d * 64 + c0;
    float* out1 = out + (row0 + 8) * DIM + d * 64 + c0;
    #pragma unroll
    for (int nt = 0; nt < 8; nt++) {
        float2 w0 = make_float2(o[nt*4+0] * i0, o[nt*4+1] * i0);
        float2 w1 = make_float2(o[nt*4+2] * i1, o[nt*4+3] * i1);
        *reinterpret_cast<float2*>(out0 + nt * 8) = w0;
        *reinterpret_cast<float2*>(out1 + nt * 8) = w1;
    }
}

// ---------------- launch ----------------
extern "C" void kernel_launch(void* const* d_in, const int* in_sizes, int n_in,
                              void* d_out, int out_size) {
    (void)in_sizes; (void)n_in; (void)out_size;
    const float* x1  = (const float*)d_in[0];
    const float* x2  = (const float*)d_in[1];
    const float* x3  = (const float*)d_in[2];
    const float* sfp = (const float*)d_in[4];
    float* out = (float*)d_out;

    cudaFuncSetAttribute(fa_fwd, cudaFuncAttributeMaxDynamicSharedMemorySize, SMEM_BYTES);

    prepass<<<(int)((NEL / 8 + 511) / 512), 512>>>(x2, x3);
    fa_fwd<<<NB * (SEQ / 128), 512, SMEM_BYTES>>>(x1, sfp, out);
}

// round 17
// speedup vs baseline: 1.2108x; 1.2108x over previous
#include <cuda_runtime.h>
#include <cuda_bf16.h>
#include <cuda_fp16.h>
#include <cstdint>

// ---------------- problem constants ----------------
static constexpr int NB  = 16;
static constexpr int SEQ = 2048;
static constexpr int DIM = 128;
static constexpr size_t NEL = (size_t)NB * SEQ * DIM;   // 4,194,304

// BLOCK_M=128 (8 warps x 16 rows), BLOCK_N=64, 32 iters, 2-stage ring
static constexpr int BLK_N   = 64;
static constexpr int NIT     = SEQ / BLK_N;             // 32
static constexpr uint32_t ROWB    = 272;                // 256B data + 16B pad (conflict-free ldmatrix)
static constexpr uint32_t TILE_B  = 64 * ROWB;          // 17408
static constexpr uint32_t STAGE_B = 3 * TILE_B;         // Khi, Klo, Vh = 52224
// smem: Qhi[128 x ROWB] + Qlo[128 x ROWB] + 2-stage ring
static constexpr uint32_t QTILE_B = 128 * ROWB;         // 34816
static constexpr uint32_t SM_QHI  = 0;
static constexpr uint32_t SM_QLO  = QTILE_B;
static constexpr uint32_t SM_RING = 2 * QTILE_B;        // 69632
static constexpr uint32_t SMEM_BYTES = SM_RING + 2 * STAGE_B;  // 174080

// ---------------- static device scratch (no allocs) ----------------
__device__ __align__(256) __nv_bfloat16 g_Khi[NEL];
__device__ __align__(256) __nv_bfloat16 g_Klo[NEL];
__device__ __align__(256) __half        g_Vh [NEL];

// ---------------- PTX helpers (base compute_103) ----------------
__device__ __forceinline__ uint32_t smem_u32(const void* p) {
    uint32_t a;
    asm("{ .reg .u64 t; cvta.to.shared.u64 t, %1; cvt.u32.u64 %0, t; }" : "=r"(a) : "l"(p));
    return a;
}
#define CP16(sm, gp) asm volatile("cp.async.cg.shared.global [%0], [%1], 16;" :: "r"(sm), "l"(gp))
#define CP_COMMIT()  asm volatile("cp.async.commit_group;" ::: "memory")
#define CP_WAIT1()   asm volatile("cp.async.wait_group 1;" ::: "memory")
#define CP_WAIT0()   asm volatile("cp.async.wait_group 0;" ::: "memory")

__device__ __forceinline__ void ldm_x4(uint32_t* r, uint32_t addr) {
    asm volatile("ldmatrix.sync.aligned.m8n8.x4.shared.b16 {%0,%1,%2,%3}, [%4];"
                 : "=r"(r[0]), "=r"(r[1]), "=r"(r[2]), "=r"(r[3]) : "r"(addr) : "memory");
}
__device__ __forceinline__ void ldm_x4_t(uint32_t* r, uint32_t addr) {
    asm volatile("ldmatrix.sync.aligned.m8n8.x4.trans.shared.b16 {%0,%1,%2,%3}, [%4];"
                 : "=r"(r[0]), "=r"(r[1]), "=r"(r[2]), "=r"(r[3]) : "r"(addr) : "memory");
}
__device__ __forceinline__ void mma_bf16(float* d, const uint32_t* a, uint32_t b0, uint32_t b1) {
    asm volatile("mma.sync.aligned.m16n8k16.row.col.f32.bf16.bf16.f32 "
                 "{%0,%1,%2,%3}, {%4,%5,%6,%7}, {%8,%9}, {%0,%1,%2,%3};"
                 : "+f"(d[0]), "+f"(d[1]), "+f"(d[2]), "+f"(d[3])
                 : "r"(a[0]), "r"(a[1]), "r"(a[2]), "r"(a[3]), "r"(b0), "r"(b1));
}
__device__ __forceinline__ void mma_f16(float* d, const uint32_t* a, uint32_t b0, uint32_t b1) {
    asm volatile("mma.sync.aligned.m16n8k16.row.col.f32.f16.f16.f32 "
                 "{%0,%1,%2,%3}, {%4,%5,%6,%7}, {%8,%9}, {%0,%1,%2,%3};"
                 : "+f"(d[0]), "+f"(d[1]), "+f"(d[2]), "+f"(d[3])
                 : "r"(a[0]), "r"(a[1]), "r"(a[2]), "r"(a[3]), "r"(b0), "r"(b1));
}

// ---------------- pre-pass: K -> split-bf16, V -> fp16 (2x float4/thread) ----------------
__global__ void __launch_bounds__(512) prepass(const float* __restrict__ x2,
                                               const float* __restrict__ x3) {
    size_t t = (size_t)blockIdx.x * blockDim.x + threadIdx.x;   // over NEL/8
    if (t >= NEL / 8) return;

    #pragma unroll
    for (int h = 0; h < 2; h++) {
        size_t i4 = t * 2 + h;
        size_t i  = i4 * 4;
        float4 k = reinterpret_cast<const float4*>(x2)[i4];
        float4 v = reinterpret_cast<const float4*>(x3)[i4];

        float ka[4] = {k.x, k.y, k.z, k.w};
        __nv_bfloat16 kh[4], kl[4];
        __half vh[4] = {__float2half(v.x), __float2half(v.y),
                        __float2half(v.z), __float2half(v.w)};
        #pragma unroll
        for (int j = 0; j < 4; j++) {
            kh[j] = __float2bfloat16(ka[j]);
            kl[j] = __float2bfloat16(ka[j] - __bfloat162float(kh[j]));
        }
        *reinterpret_cast<uint2*>(g_Khi + i) = *reinterpret_cast<uint2*>(kh);
        *reinterpret_cast<uint2*>(g_Klo + i) = *reinterpret_cast<uint2*>(kl);
        *reinterpret_cast<uint2*>(g_Vh  + i) = *reinterpret_cast<uint2*>(vh);
    }
}

// ---------------- fused flash-attention (converged config: Q in SMEM, 2-stage ring) ----------------
__global__ void __launch_bounds__(256, 1)
fa_fwd(const float* __restrict__ x1, const float* __restrict__ sfp,
       float* __restrict__ out) {
    extern __shared__ char smem[];
    const uint32_t sb = smem_u32(smem);
    const uint32_t rb = sb + SM_RING;
    const int tid  = threadIdx.x;
    const int w    = tid >> 5;
    const int lane = tid & 31;
    const int b  = blockIdx.x >> 4;   // 16 q-tiles of 128 rows per batch
    const int qt = blockIdx.x & 15;
    const float sf = *sfp;

    // per-lane ldmatrix offsets (row stride ROWB, 16B chunks)
    const uint32_t k_lane = (uint32_t)((((lane >> 4) & 1) * 8 + (lane & 7)) * ROWB + ((lane >> 3) & 1) * 16);
    const uint32_t v_lane = (uint32_t)((((lane >> 3) & 1) * 8 + (lane & 7)) * ROWB + ((lane >> 4) & 1) * 16);
    const uint32_t q_lane = (uint32_t)((lane & 15) * ROWB + (lane >> 4) * 16)
                          + (uint32_t)(w * 16) * ROWB;   // warp's 16-row slice

    // ---- stage Q block into SMEM: fp32 -> scaled split bf16 hi/lo ----
    {
        const size_t qg = ((size_t)b * SEQ + (size_t)qt * 128) * DIM;
        #pragma unroll
        for (int i = tid; i < 128 * 64; i += 256) {       // float2 chunks
            int row = i >> 6, c2 = (i & 63) * 2;
            float2 v = *reinterpret_cast<const float2*>(x1 + qg + (size_t)row * DIM + c2);
            v.x *= sf; v.y *= sf;
            __nv_bfloat16 hx = __float2bfloat16(v.x), hy = __float2bfloat16(v.y);
            __nv_bfloat162 th; th.x = hx; th.y = hy;
            __nv_bfloat162 tl = __floats2bfloat162_rn(v.x - __bfloat162float(hx),
                                                      v.y - __bfloat162float(hy));
            uint32_t soff = (uint32_t)row * ROWB + (uint32_t)c2 * 2;
            *reinterpret_cast<uint32_t*>(smem + SM_QHI + soff) = *reinterpret_cast<uint32_t*>(&th);
            *reinterpret_cast<uint32_t*>(smem + SM_QLO + soff) = *reinterpret_cast<uint32_t*>(&tl);
        }
    }

    // ---- cp.async tile loader (256 threads) ----
    const size_t kvbase = (size_t)b * SEQ * DIM;
    auto load_tiles = [&](int stage, int kt) {
        const uint32_t s0 = rb + (uint32_t)stage * STAGE_B;
        const size_t g0 = kvbase + (size_t)kt * BLK_N * DIM;
        #pragma unroll
        for (int t = 0; t < 4; t++) {
            int c = tid + t * 256;               // 0..1023
            int row = c >> 4, col = c & 15;
            uint32_t so = (uint32_t)row * ROWB + (uint32_t)col * 16;
            size_t  go = g0 + (size_t)row * DIM + col * 8;
            CP16(s0 +            so, g_Khi + go);
            CP16(s0 + TILE_B   + so, g_Klo + go);
            CP16(s0 + 2*TILE_B + so, g_Vh  + go);
        }
    };

    float o[64];
    #pragma unroll
    for (int j = 0; j < 64; j++) o[j] = 0.0f;
    float m0 = -1e30f, m1 = -1e30f, l0 = 0.0f, l1 = 0.0f;
    float s[32];
    uint32_t pf[16];

    const int r0 = lane >> 2, c0 = (lane & 3) * 2;

    load_tiles(0, 0); CP_COMMIT();

    #pragma unroll 1
    for (int kt = 0; kt < NIT; kt++) {
        if (kt + 1 < NIT) { load_tiles((kt + 1) & 1, kt + 1); CP_COMMIT(); CP_WAIT1(); }
        else              { CP_WAIT0(); }
        __syncthreads();

        const uint32_t st = rb + (uint32_t)(kt & 1) * STAGE_B;
        const uint32_t aKhi = st + k_lane;
        const uint32_t aKlo = st + TILE_B + k_lane;
        const uint32_t aV   = st + 2 * TILE_B + v_lane;

        // ---- S = Qhi*Khi + Qlo*Khi + Qhi*Klo (Q frags streamed from SMEM) ----
        #pragma unroll
        for (int j = 0; j < 32; j++) s[j] = 0.0f;
        #pragma unroll
        for (int kk = 0; kk < 8; kk++) {
            uint32_t qh[4], ql[4];
            ldm_x4(qh, sb + SM_QHI + q_lane + (uint32_t)kk * 32);
            ldm_x4(ql, sb + SM_QLO + q_lane + (uint32_t)kk * 32);
            #pragma unroll
            for (int half = 0; half < 2; half++) {
                uint32_t kb[8];
                ldm_x4(kb,     aKhi + (uint32_t)(half*2+0) * 16 * ROWB + (uint32_t)kk * 32);
                ldm_x4(kb + 4, aKhi + (uint32_t)(half*2+1) * 16 * ROWB + (uint32_t)kk * 32);
                mma_bf16(s + (4*half)     * 4, qh, kb[0], kb[1]);
                mma_bf16(s + (4*half + 1) * 4, qh, kb[2], kb[3]);
                mma_bf16(s + (4*half + 2) * 4, qh, kb[4], kb[5]);
                mma_bf16(s + (4*half + 3) * 4, qh, kb[6], kb[7]);
                mma_bf16(s + (4*half)     * 4, ql, kb[0], kb[1]);
                mma_bf16(s + (4*half + 1) * 4, ql, kb[2], kb[3]);
                mma_bf16(s + (4*half + 2) * 4, ql, kb[4], kb[5]);
                mma_bf16(s + (4*half + 3) * 4, ql, kb[6], kb[7]);
            }
            #pragma unroll
            for (int half = 0; half < 2; half++) {
                uint32_t kb[8];
                ldm_x4(kb,     aKlo + (uint32_t)(half*2+0) * 16 * ROWB + (uint32_t)kk * 32);
                ldm_x4(kb + 4, aKlo + (uint32_t)(half*2+1) * 16 * ROWB + (uint32_t)kk * 32);
                mma_bf16(s + (4*half)     * 4, qh, kb[0], kb[1]);
                mma_bf16(s + (4*half + 1) * 4, qh, kb[2], kb[3]);
                mma_bf16(s + (4*half + 2) * 4, qh, kb[4], kb[5]);
                mma_bf16(s + (4*half + 3) * 4, qh, kb[6], kb[7]);
            }
        }

        // ---- online softmax (rows r0 and r0+8; quad lanes share a row) ----
        float mx0 = -1e30f, mx1 = -1e30f;
        #pragma unroll
        for (int j = 0; j < 8; j++) {
            mx0 = fmaxf(mx0, fmaxf(s[j*4+0], s[j*4+1]));
            mx1 = fmaxf(mx1, fmaxf(s[j*4+2], s[j*4+3]));
        }
        mx0 = fmaxf(mx0, __shfl_xor_sync(0xffffffffu, mx0, 1));
        mx0 = fmaxf(mx0, __shfl_xor_sync(0xffffffffu, mx0, 2));
        mx1 = fmaxf(mx1, __shfl_xor_sync(0xffffffffu, mx1, 1));
        mx1 = fmaxf(mx1, __shfl_xor_sync(0xffffffffu, mx1, 2));
        const float mn0 = fmaxf(m0, mx0), mn1 = fmaxf(m1, mx1);
        const float a0 = __expf(m0 - mn0), a1 = __expf(m1 - mn1);
        m0 = mn0; m1 = mn1;

        float rs0 = 0.0f, rs1 = 0.0f;
        #pragma unroll
        for (int j = 0; j < 8; j++) {
            float p0 = __expf(s[j*4+0] - mn0);
            float p1 = __expf(s[j*4+1] - mn0);
            float p2 = __expf(s[j*4+2] - mn1);
            float p3 = __expf(s[j*4+3] - mn1);
            rs0 += p0 + p1; rs1 += p2 + p3;
            __half2 h01 = __floats2half2_rn(p0, p1);
            __half2 h23 = __floats2half2_rn(p2, p3);
            pf[(j >> 1) * 4 + (j & 1) * 2 + 0] = *reinterpret_cast<uint32_t*>(&h01);
            pf[(j >> 1) * 4 + (j & 1) * 2 + 1] = *reinterpret_cast<uint32_t*>(&h23);
        }
        l0 = l0 * a0 + rs0;
        l1 = l1 * a1 + rs1;

        #pragma unroll
        for (int j = 0; j < 16; j++) {
            o[j*4+0] *= a0; o[j*4+1] *= a0;
            o[j*4+2] *= a1; o[j*4+3] *= a1;
        }

        // ---- O += P * V (fp16) ----
        #pragma unroll
        for (int kk = 0; kk < 4; kk++) {
            #pragma unroll
            for (int dh = 0; dh < 4; dh++) {
                uint32_t vb[8];
                ldm_x4_t(vb,     aV + (uint32_t)kk * 16 * ROWB + (uint32_t)(dh*2+0) * 32);
                ldm_x4_t(vb + 4, aV + (uint32_t)kk * 16 * ROWB + (uint32_t)(dh*2+1) * 32);
                mma_f16(o + (2*(dh*2+0))   * 4, pf + kk*4, vb[0], vb[1]);
                mma_f16(o + (2*(dh*2+0)+1) * 4, pf + kk*4, vb[2], vb[3]);
                mma_f16(o + (2*(dh*2+1))   * 4, pf + kk*4, vb[4], vb[5]);
                mma_f16(o + (2*(dh*2+1)+1) * 4, pf + kk*4, vb[6], vb[7]);
            }
        }
        __syncthreads();
    }

    // ---- finalize: full row sums over quad, normalize, store ----
    l0 += __shfl_xor_sync(0xffffffffu, l0, 1);
    l0 += __shfl_xor_sync(0xffffffffu, l0, 2);
    l1 += __shfl_xor_sync(0xffffffffu, l1, 1);
    l1 += __shfl_xor_sync(0xffffffffu, l1, 2);
    const float i0 = 1.0f / l0, i1 = 1.0f / l1;

    const size_t row0 = (size_t)b * SEQ + (size_t)qt * 128 + w * 16 + r0;
    float* out0 = out + row0 * DIM + c0;
    float* out1 = out + (row0 + 8) * DIM + c0;
    #pragma unroll
    for (int j = 0; j < 16; j++) {
        float2 w0 = make_float2(o[j*4+0] * i0, o[j*4+1] * i0);
        float2 w1 = make_float2(o[j*4+2] * i1, o[j*4+3] * i1);
        *reinterpret_cast<float2*>(out0 + j * 8) = w0;
        *reinterpret_cast<float2*>(out1 + j * 8) = w1;
    }
}

// ---------------- launch ----------------
extern "C" void kernel_launch(void* const* d_in, const int* in_sizes, int n_in,
                              void* d_out, int out_size) {
    (void)in_sizes; (void)n_in; (void)out_size;
    const float* x1  = (const float*)d_in[0];
    const float* x2  = (const float*)d_in[1];
    const float* x3  = (const float*)d_in[2];
    const float* sfp = (const float*)d_in[4];
    float* out = (float*)d_out;

    cudaFuncSetAttribute(fa_fwd, cudaFuncAttributeMaxDynamicSharedMemorySize, SMEM_BYTES);

    prepass<<<(int)((NEL / 8 + 511) / 512), 512>>>(x2, x3);
    fa_fwd<<<NB * (SEQ / 128), 256, SMEM_BYTES>>>(x1, sfp, out);
}